// round 15
// baseline (speedup 1.0000x reference)
#include <cuda_runtime.h>
#include <cuda_fp16.h>
#include <cstdint>

// Fixed problem shape
#define NB    2
#define CCH   64
#define LL    4096
#define HEADS 2
#define DKK   64
#define DVV   32
#define NHH   4
#define NSPLIT 2
#define KT_PER_SPLIT (LL / 64 / NSPLIT)   // 32

// Q,K in e4m3 (Q pre-scaled by log2e), [nh][L][64] bytes. V fp16 [nh][L][32].
__device__ __align__(256) uint8_t Qf8[NHH * LL * 64];
__device__ __align__(256) uint8_t Kf8[NHH * LL * 64];
__device__ __half Vh[NHH * LL * DVV];
__device__ float  Og[NSPLIT * NB * LL * (HEADS * DVV)];  // unnormalized partials
__device__ float  Zg[NSPLIT * NHH * LL];                 // partial row sums

// ---------------------------------------------------------------------------
// PTX helpers
// ---------------------------------------------------------------------------
__device__ __forceinline__ void ldsm4(uint32_t& r0, uint32_t& r1, uint32_t& r2, uint32_t& r3, uint32_t a) {
    asm volatile("ldmatrix.sync.aligned.m8n8.x4.shared.b16 {%0,%1,%2,%3}, [%4];\n"
                 : "=r"(r0), "=r"(r1), "=r"(r2), "=r"(r3) : "r"(a));
}
__device__ __forceinline__ void ldsm4t(uint32_t& r0, uint32_t& r1, uint32_t& r2, uint32_t& r3, uint32_t a) {
    asm volatile("ldmatrix.sync.aligned.m8n8.x4.trans.shared.b16 {%0,%1,%2,%3}, [%4];\n"
                 : "=r"(r0), "=r"(r1), "=r"(r2), "=r"(r3) : "r"(a));
}
__device__ __forceinline__ void mma16816(float* c, const uint32_t* a, uint32_t b0, uint32_t b1) {
    asm volatile("mma.sync.aligned.m16n8k16.row.col.f32.f16.f16.f32 "
                 "{%0,%1,%2,%3}, {%4,%5,%6,%7}, {%8,%9}, {%0,%1,%2,%3};\n"
                 : "+f"(c[0]), "+f"(c[1]), "+f"(c[2]), "+f"(c[3])
                 : "r"(a[0]), "r"(a[1]), "r"(a[2]), "r"(a[3]), "r"(b0), "r"(b1));
}
__device__ __forceinline__ void mmafp8(float* c, const uint32_t* a, uint32_t b0, uint32_t b1) {
    asm volatile("mma.sync.aligned.m16n8k32.row.col.f32.e4m3.e4m3.f32 "
                 "{%0,%1,%2,%3}, {%4,%5,%6,%7}, {%8,%9}, {%0,%1,%2,%3};\n"
                 : "+f"(c[0]), "+f"(c[1]), "+f"(c[2]), "+f"(c[3])
                 : "r"(a[0]), "r"(a[1]), "r"(a[2]), "r"(a[3]), "r"(b0), "r"(b1));
}
__device__ __forceinline__ uint32_t ex2h2(float x, float y) {
    __half2 h = __floats2half2_rn(x, y);
    uint32_t in = *(uint32_t*)&h, r;
    asm("ex2.approx.f16x2 %0, %1;\n" : "=r"(r) : "r"(in));
    return r;
}
// e4m3(v) in low byte (PTX cvt d,a,b: a->hi, b->lo)
__device__ __forceinline__ uint32_t f32_to_e4m3(float v) {
    uint16_t r;
    asm("cvt.rn.satfinite.e4m3x2.f32 %0, %1, %2;\n" : "=h"(r) : "f"(0.f), "f"(v));
    return (uint32_t)(r & 0xFF);
}
__device__ __forceinline__ void cp16(uint32_t saddr, const void* g) {
    asm volatile("cp.async.cg.shared.global [%0], [%1], 16;\n" :: "r"(saddr), "l"(g));
}
__device__ __forceinline__ void cp_commit() {
    asm volatile("cp.async.commit_group;\n" ::: "memory");
}
template<int N>
__device__ __forceinline__ void cp_wait() {
    asm volatile("cp.async.wait_group %0;\n" :: "n"(N) : "memory");
}

// ---------------------------------------------------------------------------
// Kernel A: HMMA QKV projection + bias + (Q,K) L2-normalize.
// Q,K stored e4m3 (Q also scaled by log2e); V stored fp16.
// grid (64, NB, 6), block 256 (8 warps).
// ---------------------------------------------------------------------------
#define XP  72
#define WP  72
#define SGP 72      // staging buffer size basis (halves); fp8 path reuses as bytes pitch 80
#define VGP 40

__global__ __launch_bounds__(256) void qkvn_kernel(
    const float* __restrict__ x,
    const float* __restrict__ Wq, const float* __restrict__ bq,
    const float* __restrict__ Wk, const float* __restrict__ bk,
    const float* __restrict__ Wv, const float* __restrict__ bv)
{
    __shared__ __align__(16) __half xh[64 * XP];   // [c][l]
    __shared__ __align__(16) __half wh[64 * WP];   // [row][c]
    __shared__ __align__(16) __half stg[64 * SGP]; // staging [l][d]
    __shared__ float part[4][64];
    __shared__ float scl[64];

    const int lt = blockIdx.x, n = blockIdx.y, z = blockIdx.z;
    const int h = z / 3, sec = z % 3;
    const int nh = n * HEADS + h;
    const int l0 = lt * 64;
    const int tid = threadIdx.x;
    const int warp = tid >> 5, lane = tid & 31;
    const int j = tid & 63, rg = tid >> 6;
    const int m = lane >> 3, rw = lane & 7;
    const int r = lane >> 2, q = lane & 3;

    const float* W; const float* bptr; int rows; float extra;
    if (sec == 0)      { W = Wq + h * DKK * CCH; bptr = bq + h * DKK; rows = 64; extra = 1.44269504f; }
    else if (sec == 1) { W = Wk + h * DKK * CCH; bptr = bk + h * DKK; rows = 64; extra = 1.0f; }
    else               { W = Wv + h * DVV * CCH; bptr = bv + h * DVV; rows = 32; extra = 1.0f; }

    #pragma unroll
    for (int t = 0; t < 16; t++) {
        int c = rg + 4 * t;
        xh[c * XP + j] = __float2half_rn(x[((size_t)(n * CCH + c)) * LL + l0 + j]);
    }
    for (int idx = tid; idx < rows * 64; idx += 256)
        wh[(idx >> 6) * WP + (idx & 63)] = __float2half_rn(W[idx]);
    __syncthreads();

    if (rows == 64) {
        uint8_t* outq = (sec == 0 ? Qf8 : Kf8) + (size_t)nh * LL * 64;
        uint8_t* stg8 = (uint8_t*)stg;   // [l][d] bytes, pitch 80
        const int rowg = warp & 3;
        const int lhalf = warp >> 2;

        uint32_t aw[4][4];
        #pragma unroll
        for (int kc = 0; kc < 4; kc++) {
            uint32_t addr = (uint32_t)__cvta_generic_to_shared(
                &wh[(rowg * 16 + (m & 1) * 8 + rw) * WP + kc * 16 + (m >> 1) * 8]);
            ldsm4(aw[kc][0], aw[kc][1], aw[kc][2], aw[kc][3], addr);
        }

        float sacc[4][4] = {};
        #pragma unroll
        for (int kc = 0; kc < 4; kc++) {
            #pragma unroll
            for (int p = 0; p < 2; p++) {
                uint32_t b0, b1, b2, b3;
                uint32_t addr = (uint32_t)__cvta_generic_to_shared(
                    &xh[(kc * 16 + (m & 1) * 8 + rw) * XP + lhalf * 32 + p * 16 + (m >> 1) * 8]);
                ldsm4t(b0, b1, b2, b3, addr);
                mma16816(sacc[2 * p],     aw[kc], b0, b1);
                mma16816(sacc[2 * p + 1], aw[kc], b2, b3);
            }
        }

        const float bv0 = bptr[rowg * 16 + r], bv1 = bptr[rowg * 16 + 8 + r];
        #pragma unroll
        for (int nb = 0; nb < 4; nb++) {
            sacc[nb][0] += bv0; sacc[nb][1] += bv0;
            sacc[nb][2] += bv1; sacc[nb][3] += bv1;
        }

        // L2 norm over d (always for Q/K)
        float pe[4], po[4];
        #pragma unroll
        for (int nb = 0; nb < 4; nb++) {
            pe[nb] = sacc[nb][0] * sacc[nb][0] + sacc[nb][2] * sacc[nb][2];
            po[nb] = sacc[nb][1] * sacc[nb][1] + sacc[nb][3] * sacc[nb][3];
        }
        #pragma unroll
        for (int s = 4; s <= 16; s <<= 1) {
            #pragma unroll
            for (int nb = 0; nb < 4; nb++) {
                pe[nb] += __shfl_xor_sync(0xffffffffu, pe[nb], s);
                po[nb] += __shfl_xor_sync(0xffffffffu, po[nb], s);
            }
        }
        if (r == 0) {
            #pragma unroll
            for (int nb = 0; nb < 4; nb++)
                *(float2*)&part[rowg][lhalf * 32 + nb * 8 + 2 * q] = make_float2(pe[nb], po[nb]);
        }
        __syncthreads();
        if (tid < 64) {
            float s = part[0][tid] + part[1][tid] + part[2][tid] + part[3][tid];
            scl[tid] = extra / fmaxf(sqrtf(s), 1e-6f);
        }
        __syncthreads();

        // scale + stage e4m3 [l][64B] pitch 80
        #pragma unroll
        for (int nb = 0; nb < 4; nb++) {
            int lc = lhalf * 32 + nb * 8 + 2 * q;
            float se = scl[lc], so = scl[lc + 1];
            int d0 = rowg * 16 + r, d1 = d0 + 8;
            stg8[lc * 80 + d0]       = (uint8_t)f32_to_e4m3(sacc[nb][0] * se);
            stg8[(lc + 1) * 80 + d0] = (uint8_t)f32_to_e4m3(sacc[nb][1] * so);
            stg8[lc * 80 + d1]       = (uint8_t)f32_to_e4m3(sacc[nb][2] * se);
            stg8[(lc + 1) * 80 + d1] = (uint8_t)f32_to_e4m3(sacc[nb][3] * so);
        }
        __syncthreads();

        // coalesced uint4 store: [l][64B]
        {
            int l = tid >> 2, c16 = tid & 3;
            *(uint4*)&outq[(size_t)(l0 + l) * 64 + c16 * 16] = *(uint4*)&stg8[l * 80 + c16 * 16];
        }
    } else {
        __half* outh = Vh + (size_t)nh * LL * DVV;
        const int rowg = warp & 1;
        const int lq = warp >> 1;

        uint32_t aw[4][4];
        #pragma unroll
        for (int kc = 0; kc < 4; kc++) {
            uint32_t addr = (uint32_t)__cvta_generic_to_shared(
                &wh[(rowg * 16 + (m & 1) * 8 + rw) * WP + kc * 16 + (m >> 1) * 8]);
            ldsm4(aw[kc][0], aw[kc][1], aw[kc][2], aw[kc][3], addr);
        }

        float sacc[2][4] = {};
        #pragma unroll
        for (int kc = 0; kc < 4; kc++) {
            uint32_t b0, b1, b2, b3;
            uint32_t addr = (uint32_t)__cvta_generic_to_shared(
                &xh[(kc * 16 + (m & 1) * 8 + rw) * XP + lq * 16 + (m >> 1) * 8]);
            ldsm4t(b0, b1, b2, b3, addr);
            mma16816(sacc[0], aw[kc], b0, b1);
            mma16816(sacc[1], aw[kc], b2, b3);
        }

        const float bv0 = bptr[rowg * 16 + r], bv1 = bptr[rowg * 16 + 8 + r];
        #pragma unroll
        for (int nb = 0; nb < 2; nb++) {
            sacc[nb][0] += bv0; sacc[nb][1] += bv0;
            sacc[nb][2] += bv1; sacc[nb][3] += bv1;
        }

        #pragma unroll
        for (int nb = 0; nb < 2; nb++) {
            int lc = lq * 16 + nb * 8 + 2 * q;
            int d0 = rowg * 16 + r, d1 = d0 + 8;
            stg[lc * VGP + d0]       = __float2half_rn(sacc[nb][0]);
            stg[(lc + 1) * VGP + d0] = __float2half_rn(sacc[nb][1]);
            stg[lc * VGP + d1]       = __float2half_rn(sacc[nb][2]);
            stg[(lc + 1) * VGP + d1] = __float2half_rn(sacc[nb][3]);
        }
        __syncthreads();
        {
            int l = tid >> 2, c8 = tid & 3;
            *(uint4*)&outh[(size_t)(l0 + l) * 32 + c8 * 8] = *(uint4*)&stg[l * VGP + c8 * 8];
        }
    }
}

// ---------------------------------------------------------------------------
// Kernel C: flash attention, FP8 QK^T (m16n8k32 e4m3) + FP16 PV.
// Split-K, 2D warp tiling (qg x kh), 3-stage cp.async pipeline.
// grid (32, NH, 2), block 256.
// ---------------------------------------------------------------------------
#define BM 128
#define BN 64
#define QPB 80   // Q pitch bytes (5x16B -> uint4-aligned, conflict-free ldsm)
#define KPB 80   // K pitch bytes
#define VPH 40   // V pitch halves (80B)
#define RP 34    // EVEN float pitch for reduction staging
#define NSTAGE 3

__global__ __launch_bounds__(256, 2) void attn_kernel()
{
    extern __shared__ __align__(16) char smraw[];
    uint8_t* Qs8 = (uint8_t*)smraw;               // [128][QPB]
    uint8_t* Ksb = Qs8 + BM * QPB;                // [3][64][KPB]
    __half*  Vsb = (__half*)(Ksb + NSTAGE * BN * KPB);  // [3][64][VPH]
    float* red  = (float*)Ksb;                    // post-loop: [128][RP]
    float* zred = red + BM * RP;                  // [128]

    const int nh = blockIdx.y;
    const int q0 = blockIdx.x * BM;
    const int split = blockIdx.z;
    const int tid = threadIdx.x;
    const int warp = tid >> 5, lane = tid & 31;
    const int qg = warp >> 1, kh = warp & 1;
    const int m = lane >> 3, rw = lane & 7;
    const int r = lane >> 2, q = lane & 3;

    const uint8_t* Qp = Qf8 + (size_t)nh * LL * 64;
    const uint8_t* Kp = Kf8 + (size_t)nh * LL * 64;
    const __half*  Vp = Vh + (size_t)nh * LL * DVV;

    // per-thread cp.async targets: 1 K row-quarter + 1 V row-quarter each
    const int krow = tid >> 2, kc16 = tid & 3;
    uint32_t ksaddr[NSTAGE], vsaddr[NSTAGE];
    #pragma unroll
    for (int s = 0; s < NSTAGE; s++) {
        ksaddr[s] = (uint32_t)__cvta_generic_to_shared(&Ksb[s * BN * KPB + krow * KPB + kc16 * 16]);
        vsaddr[s] = (uint32_t)__cvta_generic_to_shared(&Vsb[s * BN * VPH + krow * VPH + kc16 * 8]);
    }

    // prologue: async-load tiles 0 and 1
    #pragma unroll
    for (int pre = 0; pre < 2; pre++) {
        const int k0 = (split * KT_PER_SPLIT + pre) * BN;
        cp16(ksaddr[pre], &Kp[(size_t)(k0 + krow) * 64 + kc16 * 16]);
        cp16(vsaddr[pre], &Vp[(size_t)(k0 + krow) * 32 + kc16 * 8]);
        cp_commit();
    }

    // load Q tile (128 x 64 bytes)
    #pragma unroll
    for (int t = 0; t < 2; t++) {
        int idx = tid + 256 * t;
        int row = idx >> 2, c16 = idx & 3;
        *(uint4*)&Qs8[row * QPB + c16 * 16] = *(const uint4*)&Qp[(size_t)(q0 + row) * 64 + c16 * 16];
    }
    __syncthreads();

    // loop-invariant Q fp8 A fragments: 32 rows x 64 k-bytes = mq2 x kc2
    uint32_t aq[2][2][4];
    #pragma unroll
    for (int mq = 0; mq < 2; mq++) {
        #pragma unroll
        for (int kc = 0; kc < 2; kc++) {
            int row = qg * 32 + mq * 16 + (m & 1) * 8 + rw;
            int bc = kc * 32 + (m >> 1) * 16;
            uint32_t addr = (uint32_t)__cvta_generic_to_shared(&Qs8[row * QPB + bc]);
            ldsm4(aq[mq][kc][0], aq[mq][kc][1], aq[mq][kc][2], aq[mq][kc][3], addr);
        }
    }

    float oacc[2][4][4] = {};
    float zlo[2] = {0.f, 0.f}, zhi[2] = {0.f, 0.f};

    int stage = 0;
    for (int i = 0; i < KT_PER_SPLIT; i++) {
        if (i + 1 < KT_PER_SPLIT) cp_wait<1>(); else cp_wait<0>();
        __syncthreads();

        if (i + 2 < KT_PER_SPLIT) {
            const int s = (stage + 2) % NSTAGE;
            const int k0n = (split * KT_PER_SPLIT + i + 2) * BN;
            cp16(ksaddr[s], &Kp[(size_t)(k0n + krow) * 64 + kc16 * 16]);
            cp16(vsaddr[s], &Vp[(size_t)(k0n + krow) * 32 + kc16 * 8]);
            cp_commit();
        }

        const uint8_t* Kb = Ksb + stage * BN * KPB;
        const __half*  Vb = Vsb + stage * BN * VPH;

        // ---- S = Q K^T (fp8): 32q x 32k, kc2 x p2, 4 mma each ----
        float sacc[2][4][4] = {};
        #pragma unroll
        for (int kc = 0; kc < 2; kc++) {
            #pragma unroll
            for (int p = 0; p < 2; p++) {
                int row = kh * 32 + p * 16 + (m >> 1) * 8 + rw;   // key
                int bc = kc * 32 + (m & 1) * 16;                  // k bytes
                uint32_t b0, b1, b2, b3;
                uint32_t addr = (uint32_t)__cvta_generic_to_shared(&Kb[row * KPB + bc]);
                ldsm4(b0, b1, b2, b3, addr);
                #pragma unroll
                for (int mq = 0; mq < 2; mq++) {
                    mmafp8(sacc[mq][2 * p],     aq[mq][kc], b0, b1);
                    mmafp8(sacc[mq][2 * p + 1], aq[mq][kc], b2, b3);
                }
            }
        }

        // ---- P = 2^S (Q pre-scaled by log2e); Z on the FMA pipe ----
        uint32_t ap[2][2][4];
        #pragma unroll
        for (int mq = 0; mq < 2; mq++) {
            #pragma unroll
            for (int p = 0; p < 2; p++) {
                ap[mq][p][0] = ex2h2(sacc[mq][2 * p][0],     sacc[mq][2 * p][1]);
                ap[mq][p][1] = ex2h2(sacc[mq][2 * p][2],     sacc[mq][2 * p][3]);
                ap[mq][p][2] = ex2h2(sacc[mq][2 * p + 1][0], sacc[mq][2 * p + 1][1]);
                ap[mq][p][3] = ex2h2(sacc[mq][2 * p + 1][2], sacc[mq][2 * p + 1][3]);
            }
        }
        #pragma unroll
        for (int mq = 0; mq < 2; mq++) {
            #pragma unroll
            for (int p = 0; p < 2; p++) {
                float2 f0 = __half22float2(*(__half2*)&ap[mq][p][0]);
                float2 f1 = __half22float2(*(__half2*)&ap[mq][p][1]);
                float2 f2 = __half22float2(*(__half2*)&ap[mq][p][2]);
                float2 f3 = __half22float2(*(__half2*)&ap[mq][p][3]);
                zlo[mq] += (f0.x + f0.y) + (f2.x + f2.y);
                zhi[mq] += (f1.x + f1.y) + (f3.x + f3.y);
            }
        }

        // ---- O += P V (fp16) ----
        #pragma unroll
        for (int p = 0; p < 2; p++) {
            #pragma unroll
            for (int vb = 0; vb < 2; vb++) {
                int row = kh * 32 + p * 16 + (m & 1) * 8 + rw;
                int col = vb * 16 + (m >> 1) * 8;
                uint32_t b0, b1, b2, b3;
                uint32_t addr = (uint32_t)__cvta_generic_to_shared(&Vb[row * VPH + col]);
                ldsm4t(b0, b1, b2, b3, addr);
                #pragma unroll
                for (int mq = 0; mq < 2; mq++) {
                    mma16816(oacc[mq][2 * vb],     ap[mq][p], b0, b1);
                    mma16816(oacc[mq][2 * vb + 1], ap[mq][p], b2, b3);
                }
            }
        }

        stage = (stage + 1) % NSTAGE;
    }

    #pragma unroll
    for (int mq = 0; mq < 2; mq++) {
        zlo[mq] += __shfl_xor_sync(0xffffffffu, zlo[mq], 1);
        zlo[mq] += __shfl_xor_sync(0xffffffffu, zlo[mq], 2);
        zhi[mq] += __shfl_xor_sync(0xffffffffu, zhi[mq], 1);
        zhi[mq] += __shfl_xor_sync(0xffffffffu, zhi[mq], 2);
    }

    // ---- cross-warp (kh) combine via smem, then store partials ----
    __syncthreads();
    if (kh == 1) {
        #pragma unroll
        for (int mq = 0; mq < 2; mq++) {
            int row = qg * 32 + mq * 16 + r;
            #pragma unroll
            for (int nb = 0; nb < 4; nb++) {
                *(float2*)&red[row * RP + nb * 8 + 2 * q] =
                    make_float2(oacc[mq][nb][0], oacc[mq][nb][1]);
                *(float2*)&red[(row + 8) * RP + nb * 8 + 2 * q] =
                    make_float2(oacc[mq][nb][2], oacc[mq][nb][3]);
            }
            if (q == 0) {
                zred[row]     = zlo[mq];
                zred[row + 8] = zhi[mq];
            }
        }
    }
    __syncthreads();
    if (kh == 0) {
        const int n = nh >> 1, h = nh & 1;
        #pragma unroll
        for (int mq = 0; mq < 2; mq++) {
            int row = qg * 32 + mq * 16 + r;
            if (q == 0) {
                Zg[((size_t)split * NHH + nh) * LL + q0 + row]     = zlo[mq] + zred[row];
                Zg[((size_t)split * NHH + nh) * LL + q0 + row + 8] = zhi[mq] + zred[row + 8];
            }
            #pragma unroll
            for (int nb = 0; nb < 4; nb++) {
                int dv = nb * 8 + 2 * q;
                float2 r0 = *(float2*)&red[row * RP + dv];
                float2 r1 = *(float2*)&red[(row + 8) * RP + dv];
                *(float2*)&Og[((size_t)(split * NB + n) * LL + q0 + row) * 64 + h * 32 + dv] =
                    make_float2(oacc[mq][nb][0] + r0.x, oacc[mq][nb][1] + r0.y);
                *(float2*)&Og[((size_t)(split * NB + n) * LL + q0 + row + 8) * 64 + h * 32 + dv] =
                    make_float2(oacc[mq][nb][2] + r1.x, oacc[mq][nb][3] + r1.y);
            }
        }
    }
}

// ---------------------------------------------------------------------------
// Kernel D: split combine + output projection + bias + residual.
// grid (128, NB), block 256. (R11 proven version)
// ---------------------------------------------------------------------------
__global__ __launch_bounds__(256) void out_kernel(
    const float* __restrict__ x,
    const float* __restrict__ Wm, const float* __restrict__ bm,
    float* __restrict__ out)
{
    __shared__ float Rst[64][33];
    __shared__ float wm[64][64];
    __shared__ float zinv[2][32];
    const int lt = blockIdx.x, n = blockIdx.y;
    const int l0 = lt * 32;
    const int tid = threadIdx.x;
    const int j = tid & 31, rg = tid >> 5;

    if (tid < 64) {
        int h = tid >> 5, li = tid & 31;
        float z = Zg[((size_t)0 * NHH + n * HEADS + h) * LL + l0 + li]
                + Zg[((size_t)1 * NHH + n * HEADS + h) * LL + l0 + li];
        zinv[h][li] = 1.0f / z;
    }
    #pragma unroll
    for (int t = 0; t < 16; t++) {
        int idx = tid + 256 * t;
        wm[idx >> 6][idx & 63] = Wm[idx];
    }
    __syncthreads();

    #pragma unroll
    for (int t = 0; t < 8; t++) {
        int idx = tid + 256 * t;
        int l = idx >> 6, d = idx & 63;
        float o = Og[((size_t)(0 * NB + n) * LL + l0 + l) * 64 + d]
                + Og[((size_t)(1 * NB + n) * LL + l0 + l) * 64 + d];
        Rst[d][l] = o * zinv[d >> 5][l];
    }
    __syncthreads();

    float accs[8];
    #pragma unroll
    for (int u = 0; u < 8; u++) accs[u] = bm[rg * 8 + u];
    #pragma unroll
    for (int d = 0; d < 64; d++) {
        float rv = Rst[d][j];
        #pragma unroll
        for (int u = 0; u < 8; u++) accs[u] += wm[rg * 8 + u][d] * rv;
    }
    #pragma unroll
    for (int u = 0; u < 8; u++) {
        int c = rg * 8 + u;
        size_t idx = ((size_t)(n * CCH + c)) * LL + l0 + j;
        out[idx] = accs[u] + x[idx];
    }
}

// ---------------------------------------------------------------------------
extern "C" void kernel_launch(void* const* d_in, const int* in_sizes, int n_in,
                              void* d_out, int out_size)
{
    const float* x  = (const float*)d_in[0];
    const float* Wq = (const float*)d_in[1];
    const float* bq = (const float*)d_in[2];
    const float* Wk = (const float*)d_in[3];
    const float* bk = (const float*)d_in[4];
    const float* Wv = (const float*)d_in[5];
    const float* bv = (const float*)d_in[6];
    const float* Wm = (const float*)d_in[7];
    const float* bm = (const float*)d_in[8];
    float* out = (float*)d_out;

    qkvn_kernel<<<dim3(64, NB, 6), 256>>>(x, Wq, bq, Wk, bk, Wv, bv);

    const size_t smB = (size_t)BM * QPB + (size_t)NSTAGE * BN * KPB + (size_t)NSTAGE * BN * VPH * sizeof(__half);
    cudaFuncSetAttribute(attn_kernel, cudaFuncAttributeMaxDynamicSharedMemorySize, (int)smB);
    attn_kernel<<<dim3(LL / BM, NHH, NSPLIT), 256, smB>>>();

    out_kernel<<<dim3(128, NB), 256>>>(x, Wm, bm, out);
}

// round 17
// speedup vs baseline: 1.0852x; 1.0852x over previous
#include <cuda_runtime.h>
#include <cuda_fp16.h>
#include <cstdint>

// Fixed problem shape
#define NB    2
#define CCH   64
#define LL    4096
#define HEADS 2
#define DKK   64
#define DVV   32
#define NHH   4
#define NSPLIT 4
#define KT_PER_SPLIT (LL / 64 / NSPLIT)   // 16

// fp16 activations, l-major: [nh][L][dk]. Q is pre-scaled by log2(e).
__device__ __half Qh[NHH * LL * DKK];
__device__ __half Kh[NHH * LL * DKK];
__device__ __half Vh[NHH * LL * DVV];
__device__ float  Og[NSPLIT * NB * LL * (HEADS * DVV)];  // unnormalized partials
__device__ float  Zg[NSPLIT * NHH * LL];                 // partial row sums

// ---------------------------------------------------------------------------
// PTX helpers
// ---------------------------------------------------------------------------
__device__ __forceinline__ void ldsm4(uint32_t& r0, uint32_t& r1, uint32_t& r2, uint32_t& r3, uint32_t a) {
    asm volatile("ldmatrix.sync.aligned.m8n8.x4.shared.b16 {%0,%1,%2,%3}, [%4];\n"
                 : "=r"(r0), "=r"(r1), "=r"(r2), "=r"(r3) : "r"(a));
}
__device__ __forceinline__ void ldsm4t(uint32_t& r0, uint32_t& r1, uint32_t& r2, uint32_t& r3, uint32_t a) {
    asm volatile("ldmatrix.sync.aligned.m8n8.x4.trans.shared.b16 {%0,%1,%2,%3}, [%4];\n"
                 : "=r"(r0), "=r"(r1), "=r"(r2), "=r"(r3) : "r"(a));
}
__device__ __forceinline__ void mma16816(float* c, const uint32_t* a, uint32_t b0, uint32_t b1) {
    asm volatile("mma.sync.aligned.m16n8k16.row.col.f32.f16.f16.f32 "
                 "{%0,%1,%2,%3}, {%4,%5,%6,%7}, {%8,%9}, {%0,%1,%2,%3};\n"
                 : "+f"(c[0]), "+f"(c[1]), "+f"(c[2]), "+f"(c[3])
                 : "r"(a[0]), "r"(a[1]), "r"(a[2]), "r"(a[3]), "r"(b0), "r"(b1));
}
__device__ __forceinline__ uint32_t ex2h2(float x, float y) {
    __half2 h = __floats2half2_rn(x, y);
    uint32_t in = *(uint32_t*)&h, r;
    asm("ex2.approx.f16x2 %0, %1;\n" : "=r"(r) : "r"(in));
    return r;
}

// ---------------------------------------------------------------------------
// Kernel A: HMMA QKV projection + bias + (Q,K) L2-normalize + fp16 store.
// One (head,section) job per block-z. grid (64, NB, 6), block 256. (R11)
// ---------------------------------------------------------------------------
#define XP  72
#define WP  72
#define SGP 72
#define VGP 40

__global__ __launch_bounds__(256) void qkvn_kernel(
    const float* __restrict__ x,
    const float* __restrict__ Wq, const float* __restrict__ bq,
    const float* __restrict__ Wk, const float* __restrict__ bk,
    const float* __restrict__ Wv, const float* __restrict__ bv)
{
    __shared__ __align__(16) __half xh[64 * XP];   // [c][l]
    __shared__ __align__(16) __half wh[64 * WP];   // [row][c]
    __shared__ __align__(16) __half stg[64 * SGP]; // [l][d]
    __shared__ float part[4][64];
    __shared__ float scl[64];

    const int lt = blockIdx.x, n = blockIdx.y, z = blockIdx.z;
    const int h = z / 3, sec = z % 3;
    const int nh = n * HEADS + h;
    const int l0 = lt * 64;
    const int tid = threadIdx.x;
    const int warp = tid >> 5, lane = tid & 31;
    const int j = tid & 63, rg = tid >> 6;
    const int m = lane >> 3, rw = lane & 7;
    const int r = lane >> 2, q = lane & 3;

    const float* W; const float* bptr; __half* outh; int rows; bool donorm; float extra;
    if (sec == 0)      { W = Wq + h * DKK * CCH; bptr = bq + h * DKK; outh = Qh + (size_t)nh * LL * DKK; rows = 64; donorm = true;  extra = 1.44269504f; }
    else if (sec == 1) { W = Wk + h * DKK * CCH; bptr = bk + h * DKK; outh = Kh + (size_t)nh * LL * DKK; rows = 64; donorm = true;  extra = 1.0f; }
    else               { W = Wv + h * DVV * CCH; bptr = bv + h * DVV; outh = Vh + (size_t)nh * LL * DVV; rows = 32; donorm = false; extra = 1.0f; }

    #pragma unroll
    for (int t = 0; t < 16; t++) {
        int c = rg + 4 * t;
        xh[c * XP + j] = __float2half_rn(x[((size_t)(n * CCH + c)) * LL + l0 + j]);
    }
    for (int idx = tid; idx < rows * 64; idx += 256)
        wh[(idx >> 6) * WP + (idx & 63)] = __float2half_rn(W[idx]);
    __syncthreads();

    if (rows == 64) {
        const int rowg = warp & 3;
        const int lhalf = warp >> 2;

        uint32_t aw[4][4];
        #pragma unroll
        for (int kc = 0; kc < 4; kc++) {
            uint32_t addr = (uint32_t)__cvta_generic_to_shared(
                &wh[(rowg * 16 + (m & 1) * 8 + rw) * WP + kc * 16 + (m >> 1) * 8]);
            ldsm4(aw[kc][0], aw[kc][1], aw[kc][2], aw[kc][3], addr);
        }

        float sacc[4][4] = {};
        #pragma unroll
        for (int kc = 0; kc < 4; kc++) {
            #pragma unroll
            for (int p = 0; p < 2; p++) {
                uint32_t b0, b1, b2, b3;
                uint32_t addr = (uint32_t)__cvta_generic_to_shared(
                    &xh[(kc * 16 + (m & 1) * 8 + rw) * XP + lhalf * 32 + p * 16 + (m >> 1) * 8]);
                ldsm4t(b0, b1, b2, b3, addr);
                mma16816(sacc[2 * p],     aw[kc], b0, b1);
                mma16816(sacc[2 * p + 1], aw[kc], b2, b3);
            }
        }

        const float bv0 = bptr[rowg * 16 + r], bv1 = bptr[rowg * 16 + 8 + r];
        #pragma unroll
        for (int nb = 0; nb < 4; nb++) {
            sacc[nb][0] += bv0; sacc[nb][1] += bv0;
            sacc[nb][2] += bv1; sacc[nb][3] += bv1;
        }

        if (donorm) {
            float pe[4], po[4];
            #pragma unroll
            for (int nb = 0; nb < 4; nb++) {
                pe[nb] = sacc[nb][0] * sacc[nb][0] + sacc[nb][2] * sacc[nb][2];
                po[nb] = sacc[nb][1] * sacc[nb][1] + sacc[nb][3] * sacc[nb][3];
            }
            #pragma unroll
            for (int s = 4; s <= 16; s <<= 1) {
                #pragma unroll
                for (int nb = 0; nb < 4; nb++) {
                    pe[nb] += __shfl_xor_sync(0xffffffffu, pe[nb], s);
                    po[nb] += __shfl_xor_sync(0xffffffffu, po[nb], s);
                }
            }
            if (r == 0) {
                #pragma unroll
                for (int nb = 0; nb < 4; nb++)
                    *(float2*)&part[rowg][lhalf * 32 + nb * 8 + 2 * q] = make_float2(pe[nb], po[nb]);
            }
            __syncthreads();
            if (tid < 64) {
                float s = part[0][tid] + part[1][tid] + part[2][tid] + part[3][tid];
                scl[tid] = extra / fmaxf(sqrtf(s), 1e-6f);
            }
            __syncthreads();
        }

        #pragma unroll
        for (int nb = 0; nb < 4; nb++) {
            int lc = lhalf * 32 + nb * 8 + 2 * q;
            float se = donorm ? scl[lc] : 1.0f;
            float so = donorm ? scl[lc + 1] : 1.0f;
            int d0 = rowg * 16 + r, d1 = d0 + 8;
            stg[lc * SGP + d0]       = __float2half_rn(sacc[nb][0] * se);
            stg[(lc + 1) * SGP + d0] = __float2half_rn(sacc[nb][1] * so);
            stg[lc * SGP + d1]       = __float2half_rn(sacc[nb][2] * se);
            stg[(lc + 1) * SGP + d1] = __float2half_rn(sacc[nb][3] * so);
        }
        __syncthreads();

        #pragma unroll
        for (int t = 0; t < 2; t++) {
            int idx = tid + 256 * t;
            int l = idx >> 3, c8 = idx & 7;
            *(uint4*)&outh[(size_t)(l0 + l) * 64 + c8 * 8] = *(uint4*)&stg[l * SGP + c8 * 8];
        }
    } else {
        const int rowg = warp & 1;
        const int lq = warp >> 1;

        uint32_t aw[4][4];
        #pragma unroll
        for (int kc = 0; kc < 4; kc++) {
            uint32_t addr = (uint32_t)__cvta_generic_to_shared(
                &wh[(rowg * 16 + (m & 1) * 8 + rw) * WP + kc * 16 + (m >> 1) * 8]);
            ldsm4(aw[kc][0], aw[kc][1], aw[kc][2], aw[kc][3], addr);
        }

        float sacc[2][4] = {};
        #pragma unroll
        for (int kc = 0; kc < 4; kc++) {
            uint32_t b0, b1, b2, b3;
            uint32_t addr = (uint32_t)__cvta_generic_to_shared(
                &xh[(kc * 16 + (m & 1) * 8 + rw) * XP + lq * 16 + (m >> 1) * 8]);
            ldsm4t(b0, b1, b2, b3, addr);
            mma16816(sacc[0], aw[kc], b0, b1);
            mma16816(sacc[1], aw[kc], b2, b3);
        }

        const float bv0 = bptr[rowg * 16 + r], bv1 = bptr[rowg * 16 + 8 + r];
        #pragma unroll
        for (int nb = 0; nb < 2; nb++) {
            sacc[nb][0] += bv0; sacc[nb][1] += bv0;
            sacc[nb][2] += bv1; sacc[nb][3] += bv1;
        }

        #pragma unroll
        for (int nb = 0; nb < 2; nb++) {
            int lc = lq * 16 + nb * 8 + 2 * q;
            int d0 = rowg * 16 + r, d1 = d0 + 8;
            stg[lc * VGP + d0]       = __float2half_rn(sacc[nb][0]);
            stg[(lc + 1) * VGP + d0] = __float2half_rn(sacc[nb][1]);
            stg[lc * VGP + d1]       = __float2half_rn(sacc[nb][2]);
            stg[(lc + 1) * VGP + d1] = __float2half_rn(sacc[nb][3]);
        }
        __syncthreads();
        {
            int l = tid >> 2, c8 = tid & 3;
            *(uint4*)&outh[(size_t)(l0 + l) * 32 + c8 * 8] = *(uint4*)&stg[l * VGP + c8 * 8];
        }
    }
}

// ---------------------------------------------------------------------------
// Kernel C: HMMA flash attention (R11 body), split-K over 4 key ranges.
// 2D warp tiling (qg x kh), double-buffered K/V with register prefetch.
// grid (32, NH, 4), block 256.
// ---------------------------------------------------------------------------
#define BM 128
#define BN 64
#define QP 72
#define KP 72
#define VPH 40
#define RP 34   // EVEN: float2 staging stays 8B-aligned

__global__ __launch_bounds__(256, 2) void attn_kernel()
{
    extern __shared__ __align__(16) char smraw[];
    __half* Qs  = (__half*)smraw;            // [128][QP]
    __half* Ks0 = Qs + BM * QP;              // [64][KP] buf0
    __half* Ks1 = Ks0 + BN * KP;             // [64][KP] buf1
    __half* Vs0 = Ks1 + BN * KP;             // [64][VPH] buf0
    __half* Vs1 = Vs0 + BN * VPH;            // [64][VPH] buf1
    float* red  = (float*)Ks0;               // post-loop: [128][RP]
    float* zred = red + BM * RP;             // [128]

    const int nh = blockIdx.y;
    const int q0 = blockIdx.x * BM;
    const int split = blockIdx.z;
    const int tid = threadIdx.x;
    const int warp = tid >> 5, lane = tid & 31;
    const int qg = warp >> 1, kh = warp & 1;
    const int m = lane >> 3, rw = lane & 7;
    const int r = lane >> 2, q = lane & 3;

    const __half* Qp = Qh + (size_t)nh * LL * DKK;
    const __half* Kp = Kh + (size_t)nh * LL * DKK;
    const __half* Vp = Vh + (size_t)nh * LL * DVV;

    // load Q tile + first K/V tile
    #pragma unroll
    for (int t = 0; t < 4; t++) {
        int idx = tid + 256 * t;
        int row = idx >> 3, c8 = idx & 7;
        *(uint4*)&Qs[row * QP + c8 * 8] = *(const uint4*)&Qp[(size_t)(q0 + row) * 64 + c8 * 8];
    }
    {
        const int k0 = split * KT_PER_SPLIT * BN;
        #pragma unroll
        for (int t = 0; t < 2; t++) {
            int idx = tid + 256 * t;
            int row = idx >> 3, c8 = idx & 7;
            *(uint4*)&Ks0[row * KP + c8 * 8] = *(const uint4*)&Kp[(size_t)(k0 + row) * 64 + c8 * 8];
        }
        int row = tid >> 2, c8 = tid & 3;
        *(uint4*)&Vs0[row * VPH + c8 * 8] = *(const uint4*)&Vp[(size_t)(k0 + row) * 32 + c8 * 8];
    }
    __syncthreads();

    // loop-invariant Q fragments: 32 rows (2 x m16) x 64 dk (4 x k16)
    uint32_t aq[2][4][4];
    #pragma unroll
    for (int mq = 0; mq < 2; mq++) {
        #pragma unroll
        for (int kc = 0; kc < 4; kc++) {
            int row = qg * 32 + mq * 16 + (m & 1) * 8 + rw;
            int col = kc * 16 + (m >> 1) * 8;
            uint32_t addr = (uint32_t)__cvta_generic_to_shared(&Qs[row * QP + col]);
            ldsm4(aq[mq][kc][0], aq[mq][kc][1], aq[mq][kc][2], aq[mq][kc][3], addr);
        }
    }

    float oacc[2][4][4] = {};   // [mq][dv n8 block][frag]
    float zlo[2] = {0.f, 0.f}, zhi[2] = {0.f, 0.f};

    for (int i = 0; i < KT_PER_SPLIT; i++) {
        if (i) __syncthreads();
        const __half* Kb = (i & 1) ? Ks1 : Ks0;
        const __half* Vb = (i & 1) ? Vs1 : Vs0;
        __half* Kn = (i & 1) ? Ks0 : Ks1;
        __half* Vn = (i & 1) ? Vs0 : Vs1;

        // prefetch next tile into registers (latency overlapped with compute)
        uint4 pk0, pk1, pv;
        const bool havenext = (i + 1 < KT_PER_SPLIT);
        if (havenext) {
            const int k0n = (split * KT_PER_SPLIT + i + 1) * BN;
            {
                int row = tid >> 3, c8 = tid & 7;
                pk0 = *(const uint4*)&Kp[(size_t)(k0n + row) * 64 + c8 * 8];
            }
            {
                int idx = tid + 256;
                int row = idx >> 3, c8 = idx & 7;
                pk1 = *(const uint4*)&Kp[(size_t)(k0n + row) * 64 + c8 * 8];
            }
            {
                int row = tid >> 2, c8 = tid & 3;
                pv = *(const uint4*)&Vp[(size_t)(k0n + row) * 32 + c8 * 8];
            }
        }

        // ---- S = Q K^T : 32q x 32k (keys kh*32..+31) ----
        float sacc[2][4][4] = {};
        #pragma unroll
        for (int kc = 0; kc < 4; kc++) {
            #pragma unroll
            for (int p = 0; p < 2; p++) {
                int row = kh * 32 + p * 16 + (m >> 1) * 8 + rw;
                int col = kc * 16 + (m & 1) * 8;
                uint32_t b0, b1, b2, b3;
                uint32_t addr = (uint32_t)__cvta_generic_to_shared(&Kb[row * KP + col]);
                ldsm4(b0, b1, b2, b3, addr);
                #pragma unroll
                for (int mq = 0; mq < 2; mq++) {
                    mma16816(sacc[mq][2 * p],     aq[mq][kc], b0, b1);
                    mma16816(sacc[mq][2 * p + 1], aq[mq][kc], b2, b3);
                }
            }
        }

        // ---- P = 2^S packed as A fragments; Z on the FMA pipe ----
        uint32_t ap[2][2][4];
        #pragma unroll
        for (int mq = 0; mq < 2; mq++) {
            #pragma unroll
            for (int p = 0; p < 2; p++) {
                ap[mq][p][0] = ex2h2(sacc[mq][2 * p][0],     sacc[mq][2 * p][1]);
                ap[mq][p][1] = ex2h2(sacc[mq][2 * p][2],     sacc[mq][2 * p][3]);
                ap[mq][p][2] = ex2h2(sacc[mq][2 * p + 1][0], sacc[mq][2 * p + 1][1]);
                ap[mq][p][3] = ex2h2(sacc[mq][2 * p + 1][2], sacc[mq][2 * p + 1][3]);
            }
        }
        #pragma unroll
        for (int mq = 0; mq < 2; mq++) {
            #pragma unroll
            for (int p = 0; p < 2; p++) {
                float2 f0 = __half22float2(*(__half2*)&ap[mq][p][0]);
                float2 f1 = __half22float2(*(__half2*)&ap[mq][p][1]);
                float2 f2 = __half22float2(*(__half2*)&ap[mq][p][2]);
                float2 f3 = __half22float2(*(__half2*)&ap[mq][p][3]);
                zlo[mq] += (f0.x + f0.y) + (f2.x + f2.y);
                zhi[mq] += (f1.x + f1.y) + (f3.x + f3.y);
            }
        }

        // ---- O += P V : 32q x 32dv over this warp's 32 keys ----
        #pragma unroll
        for (int p = 0; p < 2; p++) {
            #pragma unroll
            for (int vb = 0; vb < 2; vb++) {
                int row = kh * 32 + p * 16 + (m & 1) * 8 + rw;
                int col = vb * 16 + (m >> 1) * 8;
                uint32_t b0, b1, b2, b3;
                uint32_t addr = (uint32_t)__cvta_generic_to_shared(&Vb[row * VPH + col]);
                ldsm4t(b0, b1, b2, b3, addr);
                #pragma unroll
                for (int mq = 0; mq < 2; mq++) {
                    mma16816(oacc[mq][2 * vb],     ap[mq][p], b0, b1);
                    mma16816(oacc[mq][2 * vb + 1], ap[mq][p], b2, b3);
                }
            }
        }

        // store prefetched tile into the other buffer
        if (havenext) {
            {
                int row = tid >> 3, c8 = tid & 7;
                *(uint4*)&Kn[row * KP + c8 * 8] = pk0;
            }
            {
                int idx = tid + 256;
                int row = idx >> 3, c8 = idx & 7;
                *(uint4*)&Kn[row * KP + c8 * 8] = pk1;
            }
            {
                int row = tid >> 2, c8 = tid & 3;
                *(uint4*)&Vn[row * VPH + c8 * 8] = pv;
            }
        }
    }

    // Z lane reduction over the 4 q-lanes
    #pragma unroll
    for (int mq = 0; mq < 2; mq++) {
        zlo[mq] += __shfl_xor_sync(0xffffffffu, zlo[mq], 1);
        zlo[mq] += __shfl_xor_sync(0xffffffffu, zlo[mq], 2);
        zhi[mq] += __shfl_xor_sync(0xffffffffu, zhi[mq], 1);
        zhi[mq] += __shfl_xor_sync(0xffffffffu, zhi[mq], 2);
    }

    // ---- cross-warp (kh) combine via smem, then store partials ----
    __syncthreads();
    if (kh == 1) {
        #pragma unroll
        for (int mq = 0; mq < 2; mq++) {
            int row = qg * 32 + mq * 16 + r;
            #pragma unroll
            for (int nb = 0; nb < 4; nb++) {
                *(float2*)&red[row * RP + nb * 8 + 2 * q] =
                    make_float2(oacc[mq][nb][0], oacc[mq][nb][1]);
                *(float2*)&red[(row + 8) * RP + nb * 8 + 2 * q] =
                    make_float2(oacc[mq][nb][2], oacc[mq][nb][3]);
            }
            if (q == 0) {
                zred[row]     = zlo[mq];
                zred[row + 8] = zhi[mq];
            }
        }
    }
    __syncthreads();
    if (kh == 0) {
        const int n = nh >> 1, h = nh & 1;
        #pragma unroll
        for (int mq = 0; mq < 2; mq++) {
            int row = qg * 32 + mq * 16 + r;
            if (q == 0) {
                Zg[((size_t)split * NHH + nh) * LL + q0 + row]     = zlo[mq] + zred[row];
                Zg[((size_t)split * NHH + nh) * LL + q0 + row + 8] = zhi[mq] + zred[row + 8];
            }
            #pragma unroll
            for (int nb = 0; nb < 4; nb++) {
                int dv = nb * 8 + 2 * q;
                float2 r0 = *(float2*)&red[row * RP + dv];
                float2 r1 = *(float2*)&red[(row + 8) * RP + dv];
                *(float2*)&Og[((size_t)(split * NB + n) * LL + q0 + row) * 64 + h * 32 + dv] =
                    make_float2(oacc[mq][nb][0] + r0.x, oacc[mq][nb][1] + r0.y);
                *(float2*)&Og[((size_t)(split * NB + n) * LL + q0 + row + 8) * 64 + h * 32 + dv] =
                    make_float2(oacc[mq][nb][2] + r1.x, oacc[mq][nb][3] + r1.y);
            }
        }
    }
}

// ---------------------------------------------------------------------------
// Kernel D: 4-way split combine + output projection + bias + residual.
// grid (128, NB), block 256.
// ---------------------------------------------------------------------------
__global__ __launch_bounds__(256) void out_kernel(
    const float* __restrict__ x,
    const float* __restrict__ Wm, const float* __restrict__ bm,
    float* __restrict__ out)
{
    __shared__ float Rst[64][33];
    __shared__ float wm[64][64];
    __shared__ float zinv[2][32];
    const int lt = blockIdx.x, n = blockIdx.y;
    const int l0 = lt * 32;
    const int tid = threadIdx.x;
    const int j = tid & 31, rg = tid >> 5;

    if (tid < 64) {
        int h = tid >> 5, li = tid & 31;
        float z = 0.f;
        #pragma unroll
        for (int s = 0; s < NSPLIT; s++)
            z += Zg[((size_t)s * NHH + n * HEADS + h) * LL + l0 + li];
        zinv[h][li] = 1.0f / z;
    }
    #pragma unroll
    for (int t = 0; t < 16; t++) {
        int idx = tid + 256 * t;
        wm[idx >> 6][idx & 63] = Wm[idx];
    }
    __syncthreads();

    #pragma unroll
    for (int t = 0; t < 8; t++) {
        int idx = tid + 256 * t;
        int l = idx >> 6, d = idx & 63;
        float o = 0.f;
        #pragma unroll
        for (int s = 0; s < NSPLIT; s++)
            o += Og[((size_t)(s * NB + n) * LL + l0 + l) * 64 + d];
        Rst[d][l] = o * zinv[d >> 5][l];
    }
    __syncthreads();

    float accs[8];
    #pragma unroll
    for (int u = 0; u < 8; u++) accs[u] = bm[rg * 8 + u];
    #pragma unroll
    for (int d = 0; d < 64; d++) {
        float rv = Rst[d][j];
        #pragma unroll
        for (int u = 0; u < 8; u++) accs[u] += wm[rg * 8 + u][d] * rv;
    }
    #pragma unroll
    for (int u = 0; u < 8; u++) {
        int c = rg * 8 + u;
        size_t idx = ((size_t)(n * CCH + c)) * LL + l0 + j;
        out[idx] = accs[u] + x[idx];
    }
}

// ---------------------------------------------------------------------------
extern "C" void kernel_launch(void* const* d_in, const int* in_sizes, int n_in,
                              void* d_out, int out_size)
{
    const float* x  = (const float*)d_in[0];
    const float* Wq = (const float*)d_in[1];
    const float* bq = (const float*)d_in[2];
    const float* Wk = (const float*)d_in[3];
    const float* bk = (const float*)d_in[4];
    const float* Wv = (const float*)d_in[5];
    const float* bv = (const float*)d_in[6];
    const float* Wm = (const float*)d_in[7];
    const float* bm = (const float*)d_in[8];
    float* out = (float*)d_out;

    qkvn_kernel<<<dim3(64, NB, 6), 256>>>(x, Wq, bq, Wk, bk, Wv, bv);

    const size_t smB = (size_t)(BM * QP + 2 * BN * KP + 2 * BN * VPH) * sizeof(__half);
    attn_kernel<<<dim3(LL / BM, NHH, NSPLIT), 256, smB>>>();

    out_kernel<<<dim3(128, NB), 256>>>(x, Wm, bm, out);
}